// round 1
// baseline (speedup 1.0000x reference)
#include <cuda_runtime.h>
#include <cuda_bf16.h>
#include <math.h>

// Problem constants
#define BATCH 4
#define CDIM  384
#define HEADS 8
#define CH    48          // channels per head
#define HH    128
#define WW    128
#define HW    16384       // HH*WW

// ---------------------------------------------------------------------------
// Scratch buffers (device globals; no allocation allowed)
// ---------------------------------------------------------------------------
__device__ float g_tmp[(size_t)BATCH * CDIM * HW];          // pw output before dw
__device__ float g_cat[(size_t)BATCH * 2 * CDIM * HW];      // [q_dw ; qT_dw] per batch
__device__ float g_k  [(size_t)BATCH * CDIM * HW];
__device__ float g_v  [(size_t)BATCH * CDIM * HW];
__device__ float g_q  [(size_t)BATCH * CDIM * HW];
__device__ float g_attn[(size_t)BATCH * HEADS * CH * CH];
__device__ float g_invq[BATCH * CDIM];
__device__ float g_invk[BATCH * CDIM];

// ---------------------------------------------------------------------------
// SGEMM: C[b] = A (MxK, row-major weights) @ B[b] (KxN row-major)
// M % 128 == 0, N % 128 == 0, K % 8 == 0   (all true here)
// ---------------------------------------------------------------------------
#define BM 128
#define BN 128
#define BK 8
#define TM 8
#define TN 8

__global__ __launch_bounds__(256, 2)
void sgemm_kernel(const float* __restrict__ A, const float* __restrict__ Bb,
                  float* __restrict__ Cb, int M, int N, int K)
{
    const int bz = blockIdx.z;
    const float* B = Bb + (size_t)bz * K * N;
    float*       C = Cb + (size_t)bz * M * N;

    __shared__ float As[BK][BM];
    __shared__ float Bs[BK][BN];

    const int tid  = threadIdx.x;          // 256 threads
    const int tx   = tid % 16;
    const int ty   = tid / 16;
    const int brow = blockIdx.y * BM;
    const int bcol = blockIdx.x * BN;

    const int arow = tid >> 1;             // 0..127
    const int acol = (tid & 1) * 4;        // 0 or 4
    const int brl  = tid >> 5;             // 0..7
    const int bcl  = (tid & 31) * 4;       // 0..124

    float acc[TM][TN];
#pragma unroll
    for (int i = 0; i < TM; i++)
#pragma unroll
        for (int j = 0; j < TN; j++) acc[i][j] = 0.f;

    for (int k0 = 0; k0 < K; k0 += BK) {
        float4 av = *(const float4*)(A + (size_t)(brow + arow) * K + k0 + acol);
        As[acol + 0][arow] = av.x;
        As[acol + 1][arow] = av.y;
        As[acol + 2][arow] = av.z;
        As[acol + 3][arow] = av.w;
        *(float4*)&Bs[brl][bcl] =
            *(const float4*)(B + (size_t)(k0 + brl) * N + bcol + bcl);
        __syncthreads();

#pragma unroll
        for (int k = 0; k < BK; k++) {
            float4 a0 = *(const float4*)&As[k][ty * TM];
            float4 a1 = *(const float4*)&As[k][ty * TM + 4];
            float4 b0 = *(const float4*)&Bs[k][tx * TN];
            float4 b1 = *(const float4*)&Bs[k][tx * TN + 4];
            float ra[TM] = {a0.x, a0.y, a0.z, a0.w, a1.x, a1.y, a1.z, a1.w};
            float rb[TN] = {b0.x, b0.y, b0.z, b0.w, b1.x, b1.y, b1.z, b1.w};
#pragma unroll
            for (int i = 0; i < TM; i++)
#pragma unroll
                for (int j = 0; j < TN; j++) acc[i][j] += ra[i] * rb[j];
        }
        __syncthreads();
    }

#pragma unroll
    for (int i = 0; i < TM; i++) {
        const int row = brow + ty * TM + i;
        float* cp = C + (size_t)row * N + bcol + tx * TN;
        *(float4*)(cp + 0) = make_float4(acc[i][0], acc[i][1], acc[i][2], acc[i][3]);
        *(float4*)(cp + 4) = make_float4(acc[i][4], acc[i][5], acc[i][6], acc[i][7]);
    }
}

// ---------------------------------------------------------------------------
// Depthwise 3x3 SAME conv.  in: [b][c][128][128]; out with its own strides.
// ---------------------------------------------------------------------------
__global__ void dw3x3_kernel(const float* __restrict__ in, const float* __restrict__ w,
                             float* __restrict__ out,
                             size_t inBatchStride, size_t outBatchStride, int outChanOff)
{
    const int c = blockIdx.y;
    const int b = blockIdx.z;
    const float* ip = in + (size_t)b * inBatchStride + (size_t)c * HW;
    float*       op = out + (size_t)b * outBatchStride + (size_t)(c + outChanOff) * HW;
    const float* wc = w + c * 9;

    const int p = blockIdx.x * blockDim.x + threadIdx.x;
    const int y = p >> 7;
    const int x = p & 127;

    float w00 = wc[0], w01 = wc[1], w02 = wc[2];
    float w10 = wc[3], w11 = wc[4], w12 = wc[5];
    float w20 = wc[6], w21 = wc[7], w22 = wc[8];

    float s = 0.f;
    const bool t = (y > 0), bo = (y < 127), l = (x > 0), r = (x < 127);
    const float* rm = ip + (y - 1) * 128 + x;
    const float* r0 = ip + y * 128 + x;
    const float* rp = ip + (y + 1) * 128 + x;
    if (t) {
        if (l) s += rm[-1] * w00;
        s += rm[0] * w01;
        if (r) s += rm[1] * w02;
    }
    if (l) s += r0[-1] * w10;
    s += r0[0] * w11;
    if (r) s += r0[1] * w12;
    if (bo) {
        if (l) s += rp[-1] * w20;
        s += rp[0] * w21;
        if (r) s += rp[1] * w22;
    }
    op[p] = s;
}

// ---------------------------------------------------------------------------
// Row L2 inverse norm over HW:  inv[r] = 1 / max(||row||_2, 1e-12)
// ---------------------------------------------------------------------------
__global__ void rownorm_kernel(const float* __restrict__ in, float* __restrict__ inv)
{
    const int r = blockIdx.x;                 // 0 .. BATCH*CDIM-1
    const float* p = in + (size_t)r * HW;
    float s = 0.f;
    for (int i = threadIdx.x; i < HW; i += blockDim.x) {
        float v = p[i];
        s += v * v;
    }
    __shared__ float red[256];
    red[threadIdx.x] = s;
    __syncthreads();
    for (int off = 128; off > 0; off >>= 1) {
        if (threadIdx.x < off) red[threadIdx.x] += red[threadIdx.x + off];
        __syncthreads();
    }
    if (threadIdx.x == 0)
        inv[r] = 1.f / fmaxf(sqrtf(red[0]), 1e-12f);
}

// ---------------------------------------------------------------------------
// Zero attention accumulator
// ---------------------------------------------------------------------------
__global__ void zero_attn_kernel()
{
    int i = blockIdx.x * blockDim.x + threadIdx.x;
    if (i < BATCH * HEADS * CH * CH) g_attn[i] = 0.f;
}

// ---------------------------------------------------------------------------
// attn_raw[bh][c][d] += sum_n q[c][n]*k[d][n]   (split over N, atomic reduce)
// ---------------------------------------------------------------------------
#define NSPLIT 16
__global__ void attn_score_kernel(const float* __restrict__ q, const float* __restrict__ k)
{
    const int bh = blockIdx.x;                     // 0..31
    const int sp = blockIdx.y;                     // 0..NSPLIT-1
    const int b = bh >> 3, h = bh & 7;
    const float* qp = q + ((size_t)b * CDIM + h * CH) * HW;
    const float* kp = k + ((size_t)b * CDIM + h * CH) * HW;

    __shared__ float qs[CH][33];
    __shared__ float ks[CH][33];

    const int tid = threadIdx.x;                   // 256
    const int tx = tid % 16, ty = tid / 16;
    const int c0 = ty * 3, d0 = tx * 3;

    float acc[3][3] = {{0.f}};
    const int perSplit = HW / NSPLIT;              // 1024
    const int base = sp * perSplit;

    for (int t0 = 0; t0 < perSplit; t0 += 32) {
        for (int i = tid; i < CH * 32; i += 256) {
            int cc = i >> 5, kk = i & 31;
            qs[cc][kk] = qp[(size_t)cc * HW + base + t0 + kk];
            ks[cc][kk] = kp[(size_t)cc * HW + base + t0 + kk];
        }
        __syncthreads();
#pragma unroll
        for (int kk = 0; kk < 32; kk++) {
            float a0 = qs[c0 + 0][kk], a1 = qs[c0 + 1][kk], a2 = qs[c0 + 2][kk];
            float e0 = ks[d0 + 0][kk], e1 = ks[d0 + 1][kk], e2 = ks[d0 + 2][kk];
            acc[0][0] += a0 * e0; acc[0][1] += a0 * e1; acc[0][2] += a0 * e2;
            acc[1][0] += a1 * e0; acc[1][1] += a1 * e1; acc[1][2] += a1 * e2;
            acc[2][0] += a2 * e0; acc[2][1] += a2 * e1; acc[2][2] += a2 * e2;
        }
        __syncthreads();
    }

    float* ap = g_attn + (size_t)bh * CH * CH;
#pragma unroll
    for (int i = 0; i < 3; i++)
#pragma unroll
        for (int j = 0; j < 3; j++)
            atomicAdd(&ap[(c0 + i) * CH + d0 + j], acc[i][j]);
}

// ---------------------------------------------------------------------------
// Softmax with norm scaling + temperature, in place on g_attn.
// One warp per (bh, c) row.
// ---------------------------------------------------------------------------
__global__ void softmax_kernel(const float* __restrict__ invq, const float* __restrict__ invk,
                               const float* __restrict__ temp)
{
    const int r = blockIdx.x;                      // 0 .. 32*48-1
    const int bh = r / CH, c = r % CH;
    const int b = bh >> 3, h = bh & 7;
    const int lane = threadIdx.x;                  // 32

    float* row = g_attn + (size_t)bh * CH * CH + (size_t)c * CH;
    const float iq = invq[b * CDIM + h * CH + c];
    const float tp = temp[h];

    float l0 = -INFINITY, l1 = -INFINITY;
    l0 = row[lane] * iq * invk[b * CDIM + h * CH + lane] * tp;
    if (lane < CH - 32)
        l1 = row[lane + 32] * iq * invk[b * CDIM + h * CH + lane + 32] * tp;

    float m = fmaxf(l0, l1);
#pragma unroll
    for (int off = 16; off > 0; off >>= 1)
        m = fmaxf(m, __shfl_xor_sync(0xffffffff, m, off));

    float e0 = expf(l0 - m);
    float e1 = (lane < CH - 32) ? expf(l1 - m) : 0.f;
    float s = e0 + e1;
#pragma unroll
    for (int off = 16; off > 0; off >>= 1)
        s += __shfl_xor_sync(0xffffffff, s, off);

    float rs = 1.f / s;
    row[lane] = e0 * rs;
    if (lane < CH - 32) row[lane + 32] = e1 * rs;
}

// ---------------------------------------------------------------------------
// out[bh][c][p] = sum_d attn[bh][c][d] * v[bh][d][p]
// ---------------------------------------------------------------------------
__global__ __launch_bounds__(128)
void attn_out_kernel(const float* __restrict__ v, float* __restrict__ out)
{
    const int bh = blockIdx.y;
    const int b = bh >> 3, h = bh & 7;
    const int p = blockIdx.x * blockDim.x + threadIdx.x;

    __shared__ float as[CH][CH];
    for (int i = threadIdx.x; i < CH * CH; i += blockDim.x)
        as[i / CH][i % CH] = g_attn[(size_t)bh * CH * CH + i];
    __syncthreads();

    const float* vp = v + ((size_t)b * CDIM + h * CH) * HW;
    float*       op = out + ((size_t)b * CDIM + h * CH) * HW;

    float vr[CH];
#pragma unroll
    for (int d = 0; d < CH; d++) vr[d] = vp[(size_t)d * HW + p];

#pragma unroll
    for (int c = 0; c < CH; c++) {
        float s = 0.f;
#pragma unroll
        for (int d = 0; d < CH; d++) s += as[c][d] * vr[d];
        op[(size_t)c * HW + p] = s;
    }
}

// ---------------------------------------------------------------------------
// Host launcher
// ---------------------------------------------------------------------------
extern "C" void kernel_launch(void* const* d_in, const int* in_sizes, int n_in,
                              void* d_out, int out_size)
{
    const float* x      = (const float*)d_in[0];
    const float* t      = (const float*)d_in[1];
    const float* w_q    = (const float*)d_in[2];
    const float* w_q_dw = (const float*)d_in[3];
    const float* w_qT   = (const float*)d_in[4];
    const float* w_qT_dw= (const float*)d_in[5];
    const float* w_qcat = (const float*)d_in[6];
    const float* w_k    = (const float*)d_in[7];
    const float* w_k_dw = (const float*)d_in[8];
    const float* w_v    = (const float*)d_in[9];
    const float* w_v_dw = (const float*)d_in[10];
    const float* temp   = (const float*)d_in[11];
    float* out = (float*)d_out;

    float *p_tmp, *p_cat, *p_k, *p_v, *p_q, *p_invq, *p_invk;
    cudaGetSymbolAddress((void**)&p_tmp, g_tmp);
    cudaGetSymbolAddress((void**)&p_cat, g_cat);
    cudaGetSymbolAddress((void**)&p_k,   g_k);
    cudaGetSymbolAddress((void**)&p_v,   g_v);
    cudaGetSymbolAddress((void**)&p_q,   g_q);
    cudaGetSymbolAddress((void**)&p_invq, g_invq);
    cudaGetSymbolAddress((void**)&p_invk, g_invk);

    const dim3 gemmGrid(HW / BN, CDIM / BM, BATCH);   // 128 x 3 x 4
    const dim3 dwGrid(HW / 256, CDIM, BATCH);
    const size_t bsIn  = (size_t)CDIM * HW;
    const size_t bsCat = (size_t)2 * CDIM * HW;

    // q branch: pw(x, w_q) -> dw -> g_cat[:, 0:384]
    sgemm_kernel<<<gemmGrid, 256>>>(w_q, x, p_tmp, CDIM, HW, CDIM);
    dw3x3_kernel<<<dwGrid, 256>>>(p_tmp, w_q_dw, p_cat, bsIn, bsCat, 0);

    // qT branch: pw(t, w_qT) -> dw -> g_cat[:, 384:768]
    sgemm_kernel<<<gemmGrid, 256>>>(w_qT, t, p_tmp, CDIM, HW, CDIM);
    dw3x3_kernel<<<dwGrid, 256>>>(p_tmp, w_qT_dw, p_cat, bsIn, bsCat, CDIM);

    // k branch
    sgemm_kernel<<<gemmGrid, 256>>>(w_k, x, p_tmp, CDIM, HW, CDIM);
    dw3x3_kernel<<<dwGrid, 256>>>(p_tmp, w_k_dw, p_k, bsIn, bsIn, 0);

    // v branch
    sgemm_kernel<<<gemmGrid, 256>>>(w_v, x, p_tmp, CDIM, HW, CDIM);
    dw3x3_kernel<<<dwGrid, 256>>>(p_tmp, w_v_dw, p_v, bsIn, bsIn, 0);

    // q = pw(concat, w_qcat): K = 768
    sgemm_kernel<<<gemmGrid, 256>>>(w_qcat, p_cat, p_q, CDIM, HW, 2 * CDIM);

    // L2 norms
    rownorm_kernel<<<BATCH * CDIM, 256>>>(p_q, p_invq);
    rownorm_kernel<<<BATCH * CDIM, 256>>>(p_k, p_invk);

    // attention scores
    zero_attn_kernel<<<(BATCH * HEADS * CH * CH + 255) / 256, 256>>>();
    attn_score_kernel<<<dim3(BATCH * HEADS, NSPLIT), 256>>>(p_q, p_k);
    softmax_kernel<<<BATCH * HEADS * CH, 32>>>(p_invq, p_invk, temp);

    // output
    attn_out_kernel<<<dim3(HW / 128, BATCH * HEADS), 128>>>(p_v, out);
}

// round 2
// speedup vs baseline: 2.0249x; 2.0249x over previous
#include <cuda_runtime.h>
#include <cuda_bf16.h>
#include <math.h>
#include <stdint.h>

// Problem constants
#define BATCH 4
#define CDIM  384
#define HEADS 8
#define CH    48          // channels per head
#define HH    128
#define WW    128
#define HW    16384       // HH*WW

// ---------------------------------------------------------------------------
// Scratch buffers (device globals; no allocation allowed)
// ---------------------------------------------------------------------------
__device__ float g_tmp[(size_t)BATCH * CDIM * HW];          // pw output before dw
__device__ float g_cat[(size_t)BATCH * 2 * CDIM * HW];      // [q_dw ; qT_dw] per batch
__device__ float g_k  [(size_t)BATCH * CDIM * HW];
__device__ float g_v  [(size_t)BATCH * CDIM * HW];
__device__ float g_q  [(size_t)BATCH * CDIM * HW];
__device__ float g_attn[(size_t)BATCH * HEADS * CH * CH];
__device__ float g_invq[BATCH * CDIM];
__device__ float g_invk[BATCH * CDIM];

// ---------------------------------------------------------------------------
// TF32 tensor-core GEMM: C[b] = A (MxK row-major) @ B[b] (KxN row-major)
// BM=128, BN=128, BK=16; 256 threads; warp tile 64x32 via m16n8k8 tf32 mma.
// ---------------------------------------------------------------------------
#define BM 128
#define BN 128
#define BK 16
#define SSTRIDE 136   // padded row stride (floats) for conflict-free frag loads

__device__ __forceinline__ uint32_t f2tf32(float x) {
    uint32_t r;
    asm("cvt.rna.tf32.f32 %0, %1;" : "=r"(r) : "f"(x));
    return r;
}

__device__ __forceinline__ void mma_tf32(float* c, const uint32_t* a, const uint32_t* b) {
    asm volatile(
        "mma.sync.aligned.m16n8k8.row.col.f32.tf32.tf32.f32 "
        "{%0,%1,%2,%3}, {%4,%5,%6,%7}, {%8,%9}, {%0,%1,%2,%3};\n"
        : "+f"(c[0]), "+f"(c[1]), "+f"(c[2]), "+f"(c[3])
        : "r"(a[0]), "r"(a[1]), "r"(a[2]), "r"(a[3]), "r"(b[0]), "r"(b[1]));
}

__global__ __launch_bounds__(256)
void tgemm_kernel(const float* __restrict__ A, const float* __restrict__ Bb,
                  float* __restrict__ Cb, int M, int N, int K)
{
    const int bz = blockIdx.z;
    const float* B = Bb + (size_t)bz * K * N;
    float*       C = Cb + (size_t)bz * M * N;

    __shared__ uint32_t As[2][BK][SSTRIDE];   // [k][m], tf32 bits
    __shared__ uint32_t Bs[2][BK][SSTRIDE];   // [k][n], tf32 bits

    const int tid  = threadIdx.x;
    const int lane = tid & 31, warp = tid >> 5;
    const int g = lane >> 2, tig = lane & 3;
    const int wm = (warp >> 2) * 64;          // warp M offset (0/64)
    const int wn = (warp & 3) * 32;           // warp N offset (0/32/64/96)
    const int brow = blockIdx.y * BM;
    const int bcol = blockIdx.x * BN;

    // A staging: idx = tid (+256): m = idx&127, kc = (idx>>7)*4
    const int am  = tid & 127;
    const int akc = (tid >> 7) * 4;           // 0 or 4; second element adds 8
    // B staging: idx = tid (+256): kr = idx>>5, nc = (idx&31)*4
    const int bkr = tid >> 5;                 // 0..7; second element adds 8
    const int bnc = (tid & 31) * 4;

    const float* Aptr = A + (size_t)(brow + am) * K;
    const float* Bptr = B + bcol + bnc;

    float acc[4][4][4];
#pragma unroll
    for (int i = 0; i < 4; i++)
#pragma unroll
        for (int j = 0; j < 4; j++)
#pragma unroll
            for (int r = 0; r < 4; r++) acc[i][j][r] = 0.f;

    const int iters = K / BK;

    float4 aS0, aS1, bS0, bS1;
    aS0 = *(const float4*)(Aptr + akc);
    aS1 = *(const float4*)(Aptr + akc + 8);
    bS0 = *(const float4*)(Bptr + (size_t)bkr * N);
    bS1 = *(const float4*)(Bptr + (size_t)(bkr + 8) * N);

    // stash staged regs (with tf32 convert) into buffer `buf`
#define STASH(buf_)                                                          \
    do {                                                                     \
        As[buf_][akc + 0][am] = f2tf32(aS0.x);                               \
        As[buf_][akc + 1][am] = f2tf32(aS0.y);                               \
        As[buf_][akc + 2][am] = f2tf32(aS0.z);                               \
        As[buf_][akc + 3][am] = f2tf32(aS0.w);                               \
        As[buf_][akc + 8][am] = f2tf32(aS1.x);                               \
        As[buf_][akc + 9][am] = f2tf32(aS1.y);                               \
        As[buf_][akc +10][am] = f2tf32(aS1.z);                               \
        As[buf_][akc +11][am] = f2tf32(aS1.w);                               \
        uint4 p0 = make_uint4(f2tf32(bS0.x), f2tf32(bS0.y),                  \
                              f2tf32(bS0.z), f2tf32(bS0.w));                 \
        uint4 p1 = make_uint4(f2tf32(bS1.x), f2tf32(bS1.y),                  \
                              f2tf32(bS1.z), f2tf32(bS1.w));                 \
        *(uint4*)&Bs[buf_][bkr][bnc]     = p0;                               \
        *(uint4*)&Bs[buf_][bkr + 8][bnc] = p1;                               \
    } while (0)

    STASH(0);
    __syncthreads();
    int buf = 0;

    for (int it = 0; it < iters; ++it) {
        if (it + 1 < iters) {
            const float* Ap = Aptr + (it + 1) * BK;
            const float* Bp = Bptr + (size_t)((it + 1) * BK) * N;
            aS0 = *(const float4*)(Ap + akc);
            aS1 = *(const float4*)(Ap + akc + 8);
            bS0 = *(const float4*)(Bp + (size_t)bkr * N);
            bS1 = *(const float4*)(Bp + (size_t)(bkr + 8) * N);
        }

#pragma unroll
        for (int kk = 0; kk < BK; kk += 8) {
            uint32_t af[4][4], bf[4][2];
#pragma unroll
            for (int i = 0; i < 4; i++) {
                const int mr = wm + i * 16 + g;
                af[i][0] = As[buf][kk + tig    ][mr];
                af[i][1] = As[buf][kk + tig    ][mr + 8];
                af[i][2] = As[buf][kk + tig + 4][mr];
                af[i][3] = As[buf][kk + tig + 4][mr + 8];
            }
#pragma unroll
            for (int j = 0; j < 4; j++) {
                const int nr = wn + j * 8 + g;
                bf[j][0] = Bs[buf][kk + tig    ][nr];
                bf[j][1] = Bs[buf][kk + tig + 4][nr];
            }
#pragma unroll
            for (int i = 0; i < 4; i++)
#pragma unroll
                for (int j = 0; j < 4; j++)
                    mma_tf32(acc[i][j], af[i], bf[j]);
        }

        if (it + 1 < iters) {
            STASH(buf ^ 1);
            __syncthreads();
            buf ^= 1;
        }
    }
#undef STASH

    // epilogue: c0,c1 at (row, 2tig..2tig+1); c2,c3 at (row+8, ...)
#pragma unroll
    for (int i = 0; i < 4; i++) {
        const int r0 = brow + wm + i * 16 + g;
#pragma unroll
        for (int j = 0; j < 4; j++) {
            const int cc = bcol + wn + j * 8 + 2 * tig;
            *(float2*)&C[(size_t)r0 * N + cc]       = make_float2(acc[i][j][0], acc[i][j][1]);
            *(float2*)&C[(size_t)(r0 + 8) * N + cc] = make_float2(acc[i][j][2], acc[i][j][3]);
        }
    }
}

// ---------------------------------------------------------------------------
// Depthwise 3x3 SAME conv, shared-memory tiled (16 rows x 128 cols per block)
// ---------------------------------------------------------------------------
#define DTY 16
__global__ __launch_bounds__(256)
void dw3x3_kernel(const float* __restrict__ in, const float* __restrict__ w,
                  float* __restrict__ out,
                  size_t inBatchStride, size_t outBatchStride, int outChanOff)
{
    const int c = blockIdx.y;
    const int b = blockIdx.z;
    const int y0 = blockIdx.x * DTY;
    const float* ip = in + (size_t)b * inBatchStride + (size_t)c * HW;
    float*       op = out + (size_t)b * outBatchStride + (size_t)(c + outChanOff) * HW;
    const float* wc = w + c * 9;

    __shared__ float sm[DTY + 2][WW + 4];

    const int tid = threadIdx.x;
    // load (DTY+2) x (WW+2) halo region, zero padded
    for (int idx = tid; idx < (DTY + 2) * (WW + 2); idx += 256) {
        const int r  = idx / (WW + 2);
        const int cc = idx - r * (WW + 2);
        const int gy = y0 - 1 + r;
        const int gx = cc - 1;
        float v = 0.f;
        if (gy >= 0 && gy < HH && gx >= 0 && gx < WW)
            v = ip[gy * WW + gx];
        sm[r][cc] = v;
    }
    __syncthreads();

    const float w00 = wc[0], w01 = wc[1], w02 = wc[2];
    const float w10 = wc[3], w11 = wc[4], w12 = wc[5];
    const float w20 = wc[6], w21 = wc[7], w22 = wc[8];

#pragma unroll
    for (int i = 0; i < (DTY * WW) / 256; i++) {
        const int oid = tid + i * 256;
        const int y = oid >> 7;        // 0..DTY-1
        const int x = oid & 127;
        float s;
        s  = sm[y + 0][x + 0] * w00;
        s += sm[y + 0][x + 1] * w01;
        s += sm[y + 0][x + 2] * w02;
        s += sm[y + 1][x + 0] * w10;
        s += sm[y + 1][x + 1] * w11;
        s += sm[y + 1][x + 2] * w12;
        s += sm[y + 2][x + 0] * w20;
        s += sm[y + 2][x + 1] * w21;
        s += sm[y + 2][x + 2] * w22;
        op[(y0 + y) * WW + x] = s;
    }
}

// ---------------------------------------------------------------------------
// Row L2 inverse norm over HW:  inv[r] = 1 / max(||row||_2, 1e-12)
// ---------------------------------------------------------------------------
__global__ void rownorm_kernel(const float* __restrict__ in, float* __restrict__ inv)
{
    const int r = blockIdx.x;                 // 0 .. BATCH*CDIM-1
    const float* p = in + (size_t)r * HW;
    float s = 0.f;
    for (int i = threadIdx.x; i < HW / 4; i += blockDim.x) {
        float4 v = ((const float4*)p)[i];
        s += v.x * v.x + v.y * v.y + v.z * v.z + v.w * v.w;
    }
    __shared__ float red[256];
    red[threadIdx.x] = s;
    __syncthreads();
    for (int off = 128; off > 0; off >>= 1) {
        if (threadIdx.x < off) red[threadIdx.x] += red[threadIdx.x + off];
        __syncthreads();
    }
    if (threadIdx.x == 0)
        inv[r] = 1.f / fmaxf(sqrtf(red[0]), 1e-12f);
}

// ---------------------------------------------------------------------------
// Zero attention accumulator
// ---------------------------------------------------------------------------
__global__ void zero_attn_kernel()
{
    int i = blockIdx.x * blockDim.x + threadIdx.x;
    if (i < BATCH * HEADS * CH * CH) g_attn[i] = 0.f;
}

// ---------------------------------------------------------------------------
// attn_raw[bh][c][d] += sum_n q[c][n]*k[d][n]   (split over N, atomic reduce)
// ---------------------------------------------------------------------------
#define NSPLIT 16
__global__ void attn_score_kernel(const float* __restrict__ q, const float* __restrict__ k)
{
    const int bh = blockIdx.x;                     // 0..31
    const int sp = blockIdx.y;                     // 0..NSPLIT-1
    const int b = bh >> 3, h = bh & 7;
    const float* qp = q + ((size_t)b * CDIM + h * CH) * HW;
    const float* kp = k + ((size_t)b * CDIM + h * CH) * HW;

    __shared__ float qs[CH][33];
    __shared__ float ks[CH][33];

    const int tid = threadIdx.x;                   // 256
    const int tx = tid % 16, ty = tid / 16;
    const int c0 = ty * 3, d0 = tx * 3;

    float acc[3][3] = {{0.f}};
    const int perSplit = HW / NSPLIT;              // 1024
    const int base = sp * perSplit;

    for (int t0 = 0; t0 < perSplit; t0 += 32) {
        for (int i = tid; i < CH * 32; i += 256) {
            int cc = i >> 5, kk = i & 31;
            qs[cc][kk] = qp[(size_t)cc * HW + base + t0 + kk];
            ks[cc][kk] = kp[(size_t)cc * HW + base + t0 + kk];
        }
        __syncthreads();
#pragma unroll
        for (int kk = 0; kk < 32; kk++) {
            float a0 = qs[c0 + 0][kk], a1 = qs[c0 + 1][kk], a2 = qs[c0 + 2][kk];
            float e0 = ks[d0 + 0][kk], e1 = ks[d0 + 1][kk], e2 = ks[d0 + 2][kk];
            acc[0][0] += a0 * e0; acc[0][1] += a0 * e1; acc[0][2] += a0 * e2;
            acc[1][0] += a1 * e0; acc[1][1] += a1 * e1; acc[1][2] += a1 * e2;
            acc[2][0] += a2 * e0; acc[2][1] += a2 * e1; acc[2][2] += a2 * e2;
        }
        __syncthreads();
    }

    float* ap = g_attn + (size_t)bh * CH * CH;
#pragma unroll
    for (int i = 0; i < 3; i++)
#pragma unroll
        for (int j = 0; j < 3; j++)
            atomicAdd(&ap[(c0 + i) * CH + d0 + j], acc[i][j]);
}

// ---------------------------------------------------------------------------
// Softmax with norm scaling + temperature, in place on g_attn.
// One warp per (bh, c) row.
// ---------------------------------------------------------------------------
__global__ void softmax_kernel(const float* __restrict__ invq, const float* __restrict__ invk,
                               const float* __restrict__ temp)
{
    const int r = blockIdx.x;                      // 0 .. 32*48-1
    const int bh = r / CH, c = r % CH;
    const int b = bh >> 3, h = bh & 7;
    const int lane = threadIdx.x;                  // 32

    float* row = g_attn + (size_t)bh * CH * CH + (size_t)c * CH;
    const float iq = invq[b * CDIM + h * CH + c];
    const float tp = temp[h];

    float l0 = -INFINITY, l1 = -INFINITY;
    l0 = row[lane] * iq * invk[b * CDIM + h * CH + lane] * tp;
    if (lane < CH - 32)
        l1 = row[lane + 32] * iq * invk[b * CDIM + h * CH + lane + 32] * tp;

    float m = fmaxf(l0, l1);
#pragma unroll
    for (int off = 16; off > 0; off >>= 1)
        m = fmaxf(m, __shfl_xor_sync(0xffffffff, m, off));

    float e0 = expf(l0 - m);
    float e1 = (lane < CH - 32) ? expf(l1 - m) : 0.f;
    float s = e0 + e1;
#pragma unroll
    for (int off = 16; off > 0; off >>= 1)
        s += __shfl_xor_sync(0xffffffff, s, off);

    float rs = 1.f / s;
    row[lane] = e0 * rs;
    if (lane < CH - 32) row[lane + 32] = e1 * rs;
}

// ---------------------------------------------------------------------------
// out[bh][c][p] = sum_d attn[bh][c][d] * v[bh][d][p]
// ---------------------------------------------------------------------------
__global__ __launch_bounds__(128)
void attn_out_kernel(const float* __restrict__ v, float* __restrict__ out)
{
    const int bh = blockIdx.y;
    const int b = bh >> 3, h = bh & 7;
    const int p = blockIdx.x * blockDim.x + threadIdx.x;

    __shared__ float as[CH][CH];
    for (int i = threadIdx.x; i < CH * CH; i += blockDim.x)
        as[i / CH][i % CH] = g_attn[(size_t)bh * CH * CH + i];
    __syncthreads();

    const float* vp = v + ((size_t)b * CDIM + h * CH) * HW;
    float*       op = out + ((size_t)b * CDIM + h * CH) * HW;

    float vr[CH];
#pragma unroll
    for (int d = 0; d < CH; d++) vr[d] = vp[(size_t)d * HW + p];

#pragma unroll
    for (int c = 0; c < CH; c++) {
        float s = 0.f;
#pragma unroll
        for (int d = 0; d < CH; d++) s += as[c][d] * vr[d];
        op[(size_t)c * HW + p] = s;
    }
}

// ---------------------------------------------------------------------------
// Host launcher
// ---------------------------------------------------------------------------
extern "C" void kernel_launch(void* const* d_in, const int* in_sizes, int n_in,
                              void* d_out, int out_size)
{
    const float* x      = (const float*)d_in[0];
    const float* t      = (const float*)d_in[1];
    const float* w_q    = (const float*)d_in[2];
    const float* w_q_dw = (const float*)d_in[3];
    const float* w_qT   = (const float*)d_in[4];
    const float* w_qT_dw= (const float*)d_in[5];
    const float* w_qcat = (const float*)d_in[6];
    const float* w_k    = (const float*)d_in[7];
    const float* w_k_dw = (const float*)d_in[8];
    const float* w_v    = (const float*)d_in[9];
    const float* w_v_dw = (const float*)d_in[10];
    const float* temp   = (const float*)d_in[11];
    float* out = (float*)d_out;

    float *p_tmp, *p_cat, *p_k, *p_v, *p_q, *p_invq, *p_invk;
    cudaGetSymbolAddress((void**)&p_tmp, g_tmp);
    cudaGetSymbolAddress((void**)&p_cat, g_cat);
    cudaGetSymbolAddress((void**)&p_k,   g_k);
    cudaGetSymbolAddress((void**)&p_v,   g_v);
    cudaGetSymbolAddress((void**)&p_q,   g_q);
    cudaGetSymbolAddress((void**)&p_invq, g_invq);
    cudaGetSymbolAddress((void**)&p_invk, g_invk);

    const dim3 gemmGrid(HW / BN, CDIM / BM, BATCH);   // 128 x 3 x 4
    const dim3 dwGrid(HH / DTY, CDIM, BATCH);         // 8 x 384 x 4
    const size_t bsIn  = (size_t)CDIM * HW;
    const size_t bsCat = (size_t)2 * CDIM * HW;

    // q branch: pw(x, w_q) -> dw -> g_cat[:, 0:384]
    tgemm_kernel<<<gemmGrid, 256>>>(w_q, x, p_tmp, CDIM, HW, CDIM);
    dw3x3_kernel<<<dwGrid, 256>>>(p_tmp, w_q_dw, p_cat, bsIn, bsCat, 0);

    // qT branch: pw(t, w_qT) -> dw -> g_cat[:, 384:768]
    tgemm_kernel<<<gemmGrid, 256>>>(w_qT, t, p_tmp, CDIM, HW, CDIM);
    dw3x3_kernel<<<dwGrid, 256>>>(p_tmp, w_qT_dw, p_cat, bsIn, bsCat, CDIM);

    // k branch
    tgemm_kernel<<<gemmGrid, 256>>>(w_k, x, p_tmp, CDIM, HW, CDIM);
    dw3x3_kernel<<<dwGrid, 256>>>(p_tmp, w_k_dw, p_k, bsIn, bsIn, 0);

    // v branch
    tgemm_kernel<<<gemmGrid, 256>>>(w_v, x, p_tmp, CDIM, HW, CDIM);
    dw3x3_kernel<<<dwGrid, 256>>>(p_tmp, w_v_dw, p_v, bsIn, bsIn, 0);

    // q = pw(concat, w_qcat): K = 768
    tgemm_kernel<<<gemmGrid, 256>>>(w_qcat, p_cat, p_q, CDIM, HW, 2 * CDIM);

    // L2 norms
    rownorm_kernel<<<BATCH * CDIM, 256>>>(p_q, p_invq);
    rownorm_kernel<<<BATCH * CDIM, 256>>>(p_k, p_invk);

    // attention scores
    zero_attn_kernel<<<(BATCH * HEADS * CH * CH + 255) / 256, 256>>>();
    attn_score_kernel<<<dim3(BATCH * HEADS, NSPLIT), 256>>>(p_q, p_k);
    softmax_kernel<<<BATCH * HEADS * CH, 32>>>(p_invq, p_invk, temp);

    // output
    attn_out_kernel<<<dim3(HW / 128, BATCH * HEADS), 128>>>(p_v, out);
}